// round 1
// baseline (speedup 1.0000x reference)
#include <cuda_runtime.h>
#include <math.h>

// ---------------------------------------------------------------------------
// ReasonNet: 2 hops of top-K neighbor attention + LN + FFN + LN.  fp32 baseline.
// B=16, T=1024, C=1024, K=8, H=1536.  M = B*T = 16384 rows.
// ---------------------------------------------------------------------------

#define BM 128
#define BN 128
#define BKD 16
#define TM 8
#define TN 8

#define MDIM  16384
#define CDIM  1024
#define HDIM  1536
#define KNEI  8
#define TSEQ  1024

// Scratch (static device globals; no runtime allocation allowed).
__device__ float g_h  [(size_t)MDIM * CDIM];
__device__ float g_q  [(size_t)MDIM * CDIM];
__device__ float g_k  [(size_t)MDIM * CDIM];
__device__ float g_v  [(size_t)MDIM * CDIM];
__device__ float g_ctx[(size_t)MDIM * CDIM];
__device__ float g_y  [(size_t)MDIM * CDIM];
__device__ float g_hid[(size_t)MDIM * HDIM];
__device__ float g_f  [(size_t)MDIM * CDIM];

// ---------------------------------------------------------------------------
// SGEMM: C[M,N] = A[M,K] @ B[K,N]  (+bias, +relu optional).
// 128x128 tile, BK=16, 8x8 per thread, 256 threads, 2 CTAs/SM.
// All dims assumed divisible by tile sizes (true for this problem).
// ---------------------------------------------------------------------------
__global__ __launch_bounds__(256, 2)
void sgemm_kernel(const float* __restrict__ A, const float* __restrict__ B,
                  float* __restrict__ C, int M, int N, int K,
                  const float* __restrict__ bias, int do_relu)
{
    __shared__ float As[BKD][BM];   // A tile, transposed (k-major)
    __shared__ float Bs[BKD][BN];

    const int bm = blockIdx.y * BM;
    const int bn = blockIdx.x * BN;
    const int tid = threadIdx.x;
    const int tx = tid & 15;    // 0..15 -> column group
    const int ty = tid >> 4;    // 0..15 -> row group

    float acc[TM][TN];
#pragma unroll
    for (int i = 0; i < TM; i++)
#pragma unroll
        for (int j = 0; j < TN; j++) acc[i][j] = 0.f;

    const int numK = K / BKD;
    for (int kt = 0; kt < numK; kt++) {
        // Load A tile: BM x BK = 2048 floats = 512 float4, 2 per thread.
#pragma unroll
        for (int l = 0; l < 2; l++) {
            int id  = tid + l * 256;
            int row = id >> 2;            // 0..127
            int c4  = id & 3;             // 0..3 (k sub-chunk)
            float4 a = *(const float4*)(A + (size_t)(bm + row) * K + kt * BKD + c4 * 4);
            As[c4 * 4 + 0][row] = a.x;
            As[c4 * 4 + 1][row] = a.y;
            As[c4 * 4 + 2][row] = a.z;
            As[c4 * 4 + 3][row] = a.w;
        }
        // Load B tile: BK x BN = 2048 floats, fully coalesced rows.
#pragma unroll
        for (int l = 0; l < 2; l++) {
            int id  = tid + l * 256;
            int row = id >> 5;            // 0..15
            int c4  = id & 31;            // 0..31
            *((float4*)&Bs[row][c4 * 4]) =
                *(const float4*)(B + (size_t)(kt * BKD + row) * N + bn + c4 * 4);
        }
        __syncthreads();

#pragma unroll
        for (int k = 0; k < BKD; k++) {
            float ra[TM], rb[TN];
            *(float4*)&ra[0] = *(const float4*)&As[k][ty * TM];
            *(float4*)&ra[4] = *(const float4*)&As[k][ty * TM + 4];
            *(float4*)&rb[0] = *(const float4*)&Bs[k][tx * TN];
            *(float4*)&rb[4] = *(const float4*)&Bs[k][tx * TN + 4];
#pragma unroll
            for (int i = 0; i < TM; i++)
#pragma unroll
                for (int j = 0; j < TN; j++)
                    acc[i][j] = fmaf(ra[i], rb[j], acc[i][j]);
        }
        __syncthreads();
    }

    float bb[TN];
    if (bias) {
#pragma unroll
        for (int j = 0; j < TN; j++) bb[j] = bias[bn + tx * TN + j];
    } else {
#pragma unroll
        for (int j = 0; j < TN; j++) bb[j] = 0.f;
    }

#pragma unroll
    for (int i = 0; i < TM; i++) {
        float* crow = C + (size_t)(bm + ty * TM + i) * N + bn + tx * TN;
        float v[TN];
#pragma unroll
        for (int j = 0; j < TN; j++) {
            float t = acc[i][j] + bb[j];
            v[j] = do_relu ? fmaxf(t, 0.f) : t;
        }
        *(float4*)(crow)     = *(float4*)&v[0];
        *(float4*)(crow + 4) = *(float4*)&v[4];
    }
}

// ---------------------------------------------------------------------------
// Neighbor attention: one block per token (b,t), 256 threads (8 warps).
// Warp j computes score_j = <q[bt], kproj[row_j]> * (1/32) + radj[bt,j].
// Softmax over K=8, then ctx[bt] = sum_j w_j * vproj[row_j].
// ---------------------------------------------------------------------------
__global__ __launch_bounds__(256)
void attn_kernel(const float* __restrict__ q, const float* __restrict__ kp,
                 const float* __restrict__ vp, const float* __restrict__ radj,
                 const int* __restrict__ inxs, float* __restrict__ ctx)
{
    const int bt  = blockIdx.x;           // 0..16383
    const int b   = bt >> 10;             // T = 1024
    const int tid = threadIdx.x;
    const int wid = tid >> 5;
    const int lid = tid & 31;

    __shared__ float s_scores[KNEI];
    __shared__ int   s_rows[KNEI];

    if (tid < KNEI) s_rows[tid] = b * TSEQ + inxs[(size_t)bt * KNEI + tid];
    __syncthreads();

    // Warp wid: dot(q_row, k_row) over C=1024 (256 float4).
    const float4* qv = (const float4*)(q + (size_t)bt * CDIM);
    const float4* kv = (const float4*)(kp + (size_t)s_rows[wid] * CDIM);
    float sum = 0.f;
#pragma unroll 4
    for (int e = lid; e < CDIM / 4; e += 32) {
        float4 a = qv[e], c = kv[e];
        sum += a.x * c.x + a.y * c.y + a.z * c.z + a.w * c.w;
    }
#pragma unroll
    for (int o = 16; o > 0; o >>= 1) sum += __shfl_xor_sync(0xffffffffu, sum, o);
    if (lid == 0)
        s_scores[wid] = sum * 0.03125f + radj[(size_t)bt * KNEI + wid];  // 1/sqrt(1024)
    __syncthreads();

    // Softmax over 8 (every thread, registers).
    float w[KNEI];
    float mx = s_scores[0];
#pragma unroll
    for (int j = 1; j < KNEI; j++) mx = fmaxf(mx, s_scores[j]);
    float den = 0.f;
#pragma unroll
    for (int j = 0; j < KNEI; j++) { w[j] = expf(s_scores[j] - mx); den += w[j]; }
    const float inv = 1.f / den;

    // Weighted V sum: thread tid handles float4 column chunk tid.
    float4 o4 = make_float4(0.f, 0.f, 0.f, 0.f);
#pragma unroll
    for (int j = 0; j < KNEI; j++) {
        const float4 v = ((const float4*)(vp + (size_t)s_rows[j] * CDIM))[tid];
        const float wj = w[j] * inv;
        o4.x = fmaf(wj, v.x, o4.x);
        o4.y = fmaf(wj, v.y, o4.y);
        o4.z = fmaf(wj, v.z, o4.z);
        o4.w = fmaf(wj, v.w, o4.w);
    }
    ((float4*)(ctx + (size_t)bt * CDIM))[tid] = o4;
}

// ---------------------------------------------------------------------------
// LayerNorm with fused residual add (optionally relu on the second operand):
//   z = a + (relu_h ? relu(hb) : hb);  out = (z - mean)/sqrt(var+eps) * g + beta
// One block per token, 256 threads, C=1024 (one float4 per thread).
// ---------------------------------------------------------------------------
__global__ __launch_bounds__(256)
void ln_kernel(const float* __restrict__ a, const float* __restrict__ hb,
               const float* __restrict__ g, const float* __restrict__ beta,
               float* __restrict__ out, int relu_h)
{
    __shared__ float sh1[8], sh2[8];
    const int bt  = blockIdx.x;
    const int tid = threadIdx.x;
    const int wid = tid >> 5, lid = tid & 31;
    const size_t base = (size_t)bt * CDIM;

    float4 z  = ((const float4*)(a + base))[tid];
    float4 hh = ((const float4*)(hb + base))[tid];
    if (relu_h) {
        hh.x = fmaxf(hh.x, 0.f); hh.y = fmaxf(hh.y, 0.f);
        hh.z = fmaxf(hh.z, 0.f); hh.w = fmaxf(hh.w, 0.f);
    }
    z.x += hh.x; z.y += hh.y; z.z += hh.z; z.w += hh.w;

    float s  = z.x + z.y + z.z + z.w;
    float ss = z.x * z.x + z.y * z.y + z.z * z.z + z.w * z.w;
#pragma unroll
    for (int o = 16; o > 0; o >>= 1) {
        s  += __shfl_xor_sync(0xffffffffu, s, o);
        ss += __shfl_xor_sync(0xffffffffu, ss, o);
    }
    if (lid == 0) { sh1[wid] = s; sh2[wid] = ss; }
    __syncthreads();
    float ts = 0.f, tss = 0.f;
#pragma unroll
    for (int j = 0; j < 8; j++) { ts += sh1[j]; tss += sh2[j]; }

    const float mean = ts * (1.f / CDIM);
    const float var  = tss * (1.f / CDIM) - mean * mean;
    const float rstd = rsqrtf(var + 1e-5f);

    const float4 gg = ((const float4*)g)[tid];
    const float4 bb = ((const float4*)beta)[tid];
    float4 o4;
    o4.x = (z.x - mean) * rstd * gg.x + bb.x;
    o4.y = (z.y - mean) * rstd * gg.y + bb.y;
    o4.z = (z.z - mean) * rstd * gg.z + bb.z;
    o4.w = (z.w - mean) * rstd * gg.w + bb.w;
    ((float4*)(out + base))[tid] = o4;
}

// ---------------------------------------------------------------------------
// Launch
// ---------------------------------------------------------------------------
extern "C" void kernel_launch(void* const* d_in, const int* in_sizes, int n_in,
                              void* d_out, int out_size)
{
    const float* x    = (const float*)d_in[0];
    const float* radj = (const float*)d_in[1];
    const int*   inxs = (const int*)  d_in[2];
    const float* Wq   = (const float*)d_in[3];
    const float* Wk   = (const float*)d_in[4];
    const float* Wv   = (const float*)d_in[5];
    const float* Wo   = (const float*)d_in[6];
    const float* ln1g = (const float*)d_in[7];
    const float* ln1b = (const float*)d_in[8];
    const float* W1   = (const float*)d_in[9];
    const float* b1   = (const float*)d_in[10];
    const float* W2   = (const float*)d_in[11];
    const float* b2   = (const float*)d_in[12];
    const float* ln2g = (const float*)d_in[13];
    const float* ln2b = (const float*)d_in[14];
    float* out = (float*)d_out;

    float *h, *qb, *kb, *vb, *ctx, *y, *hid, *f;
    cudaGetSymbolAddress((void**)&h,   g_h);
    cudaGetSymbolAddress((void**)&qb,  g_q);
    cudaGetSymbolAddress((void**)&kb,  g_k);
    cudaGetSymbolAddress((void**)&vb,  g_v);
    cudaGetSymbolAddress((void**)&ctx, g_ctx);
    cudaGetSymbolAddress((void**)&y,   g_y);
    cudaGetSymbolAddress((void**)&hid, g_hid);
    cudaGetSymbolAddress((void**)&f,   g_f);

    const dim3 blk(256);
    const dim3 gridCC(CDIM / BN, MDIM / BM);   // (8, 128)
    const dim3 gridCH(HDIM / BN, MDIM / BM);   // (12, 128)

    const float* src = x;  // hop 0 reads x directly
    for (int hop = 0; hop < 2; hop++) {
        sgemm_kernel<<<gridCC, blk>>>(src, Wq, qb, MDIM, CDIM, CDIM, nullptr, 0);
        sgemm_kernel<<<gridCC, blk>>>(src, Wk, kb, MDIM, CDIM, CDIM, nullptr, 0);
        sgemm_kernel<<<gridCC, blk>>>(src, Wv, vb, MDIM, CDIM, CDIM, nullptr, 0);
        attn_kernel<<<MDIM, blk>>>(qb, kb, vb, radj, inxs, ctx);
        sgemm_kernel<<<gridCC, blk>>>(ctx, Wo, h, MDIM, CDIM, CDIM, nullptr, 0);
        src = h;
    }

    // y = LN(x + relu(h))
    ln_kernel<<<MDIM, blk>>>(x, h, ln1g, ln1b, y, 1);
    // hidden = relu(y @ W1 + b1)
    sgemm_kernel<<<gridCH, blk>>>(y, W1, hid, MDIM, HDIM, CDIM, b1, 1);
    // f = hidden @ W2 + b2
    sgemm_kernel<<<gridCC, blk>>>(hid, W2, f, MDIM, CDIM, HDIM, b2, 0);
    // out = LN(y + f)
    ln_kernel<<<MDIM, blk>>>(y, f, ln2g, ln2b, out, 0);
}

// round 3
// speedup vs baseline: 3.5471x; 3.5471x over previous
#include <cuda_runtime.h>
#include <cuda_fp16.h>
#include <cstdint>
#include <math.h>

// ============================================================================
// ReasonNet via portable tensor-core path (ldmatrix + mma.sync HMMA).
// fp16 2-term split (hi+lo) => fp32-accurate GEMMs: C = Ah*Bh + Ah*Bl + Al*Bh.
// B=16, T=1024, C=1024, K=8, H=1536.  M = B*T = 16384.
// ============================================================================

#define MDIM 16384
#define CDIM 1024
#define HDIM 1536
#define KNEI 8
#define TSEQ 1024

#define BK 32
#define KSTRIDE 40                  // halfs per smem row (80B: 16B-aligned, LDSM conflict-free)
#define STG_A_H 0
#define STG_A_L 10240               // 128*40*2 bytes
#define STG_B_H 20480
#define STG_B_L 30720
#define STG_BYTES 40960
#define MM_SMEM (3 * STG_BYTES)     // 122880 bytes

// ---------------------------------------------------------------------------
// Scratch (static device globals; runtime allocation forbidden).
// ---------------------------------------------------------------------------
__device__ float  g_q   [(size_t)MDIM * CDIM];
__device__ float  g_k   [(size_t)MDIM * CDIM];
__device__ float  g_v   [(size_t)MDIM * CDIM];
__device__ __half g_ctxh[(size_t)MDIM * CDIM];
__device__ __half g_ctxl[(size_t)MDIM * CDIM];
__device__ __half g_hh  [(size_t)MDIM * CDIM];
__device__ __half g_hl  [(size_t)MDIM * CDIM];
__device__ float  g_h32 [(size_t)MDIM * CDIM];
__device__ float  g_y   [(size_t)MDIM * CDIM];
__device__ __half g_yh  [(size_t)MDIM * CDIM];
__device__ __half g_yl  [(size_t)MDIM * CDIM];
__device__ float  g_f   [(size_t)MDIM * CDIM];
__device__ __half g_xh  [(size_t)MDIM * CDIM];
__device__ __half g_xl  [(size_t)MDIM * CDIM];
__device__ __half g_hidh[(size_t)MDIM * HDIM];
__device__ __half g_hidl[(size_t)MDIM * HDIM];
// Transposed + split weights: Wt[N][K] fp16 hi/lo
__device__ __half g_wqh[(size_t)CDIM * CDIM], g_wql[(size_t)CDIM * CDIM];
__device__ __half g_wkh[(size_t)CDIM * CDIM], g_wkl[(size_t)CDIM * CDIM];
__device__ __half g_wvh[(size_t)CDIM * CDIM], g_wvl[(size_t)CDIM * CDIM];
__device__ __half g_woh[(size_t)CDIM * CDIM], g_wol[(size_t)CDIM * CDIM];
__device__ __half g_w1h[(size_t)HDIM * CDIM], g_w1l[(size_t)HDIM * CDIM];
__device__ __half g_w2h[(size_t)CDIM * HDIM], g_w2l[(size_t)CDIM * HDIM];

// ---------------------------------------------------------------------------
// PTX helpers (sm_80-portable only)
// ---------------------------------------------------------------------------
__device__ __forceinline__ uint32_t smem_u32(const void* p) {
    uint32_t a;
    asm("{ .reg .u64 t; cvta.to.shared.u64 t, %1; cvt.u32.u64 %0, t; }"
        : "=r"(a) : "l"(p));
    return a;
}
__device__ __forceinline__ void cp16(uint32_t s, const void* g) {
    asm volatile("cp.async.cg.shared.global [%0], [%1], 16;" :: "r"(s), "l"(g) : "memory");
}
__device__ __forceinline__ void ldsm4(uint32_t* r, uint32_t addr) {
    asm volatile("ldmatrix.sync.aligned.m8n8.x4.shared.b16 {%0,%1,%2,%3}, [%4];"
                 : "=r"(r[0]), "=r"(r[1]), "=r"(r[2]), "=r"(r[3]) : "r"(addr));
}
__device__ __forceinline__ void mma16816(float* c, const uint32_t* a, const uint32_t* b) {
    asm volatile(
        "mma.sync.aligned.m16n8k16.row.col.f32.f16.f16.f32 "
        "{%0,%1,%2,%3}, {%4,%5,%6,%7}, {%8,%9}, {%0,%1,%2,%3};"
        : "+f"(c[0]), "+f"(c[1]), "+f"(c[2]), "+f"(c[3])
        : "r"(a[0]), "r"(a[1]), "r"(a[2]), "r"(a[3]), "r"(b[0]), "r"(b[1]));
}

// ---------------------------------------------------------------------------
// fp16-split GEMM: C[M,N] = (Ah+Al)[M,K] @ (Bh+Bl)[N,K]^T   (fp32 accuracy)
// flags: bit0 relu, bit1 write fp16 split (Chh/Chl), bit2 write fp32 (Cf).
// 256 threads, 128x128 tile, BK=32, 3-stage cp.async pipeline.
// ---------------------------------------------------------------------------
__global__ __launch_bounds__(256, 1)
void mm_fp16x2_kernel(const __half* __restrict__ Ah, const __half* __restrict__ Al,
                      const __half* __restrict__ Bh, const __half* __restrict__ Bl,
                      float* __restrict__ Cf, __half* __restrict__ Chh,
                      __half* __restrict__ Chl, const float* __restrict__ bias,
                      int N, int K, int flags)
{
    extern __shared__ char smem[];
    const uint32_t sb = smem_u32(smem);
    const int tid  = threadIdx.x;
    const int wid  = tid >> 5;
    const int lane = tid & 31;
    const int bm   = blockIdx.y * 128;
    const int bn   = blockIdx.x * 128;
    const int wmB  = (wid >> 2) * 64;
    const int wn   = (wid & 3) * 32;
    const int ntiles = K / BK;

    // -------- producer addressing (all 256 threads) --------
    const int row = tid & 127;      // tile row handled by this thread
    const int sg0 = tid >> 7;       // seg 0/1; second chunk is seg+2
    const __half* gAh = Ah + (size_t)(bm + row) * K;
    const __half* gAl = Al + (size_t)(bm + row) * K;
    const __half* gBh = Bh + (size_t)(bn + row) * K;
    const __half* gBl = Bl + (size_t)(bn + row) * K;
    const uint32_t doff = (uint32_t)row * 80;

    auto issue = [&](int kt, int s) {
        const uint32_t st = sb + (uint32_t)s * STG_BYTES;
        const size_t kof = (size_t)kt * BK;
#pragma unroll
        for (int qq = 0; qq < 2; qq++) {
            const int seg = sg0 + qq * 2;
            const uint32_t d = doff + seg * 16;
            const size_t g = kof + seg * 8;
            cp16(st + STG_A_H + d, gAh + g);
            cp16(st + STG_A_L + d, gAl + g);
            cp16(st + STG_B_H + d, gBh + g);
            cp16(st + STG_B_L + d, gBl + g);
        }
        asm volatile("cp.async.commit_group;" ::: "memory");
    };

    float acc[4][4][4];
#pragma unroll
    for (int i = 0; i < 4; i++)
#pragma unroll
        for (int j = 0; j < 4; j++)
#pragma unroll
            for (int l = 0; l < 4; l++) acc[i][j][l] = 0.f;

    issue(0, 0);
    issue(1, 1);

    // ldmatrix lane addressing (constant across tiles)
    const int arow = lane & 15;
    const int acol8 = (lane >> 4) * 8;
    const int brow = (lane & 7) + ((lane >> 4) << 3);
    const int bcol8 = ((lane >> 3) & 1) * 8;

    for (int kt = 0; kt < ntiles; kt++) {
        if (kt == ntiles - 1)
            asm volatile("cp.async.wait_group 0;" ::: "memory");
        else
            asm volatile("cp.async.wait_group 1;" ::: "memory");
        __syncthreads();

        const uint32_t stg = sb + (uint32_t)(kt % 3) * STG_BYTES;
#pragma unroll
        for (int ks = 0; ks < 2; ks++) {
            const int kb = ks * 16;
            uint32_t ahf[4][4], alf[4][4], bhf[2][4], blf[2][4];
#pragma unroll
            for (int mt = 0; mt < 4; mt++) {
                const uint32_t off =
                    (uint32_t)((wmB + mt * 16 + arow) * KSTRIDE + kb + acol8) * 2;
                ldsm4(ahf[mt], stg + STG_A_H + off);
                ldsm4(alf[mt], stg + STG_A_L + off);
            }
#pragma unroll
            for (int nt2 = 0; nt2 < 2; nt2++) {
                const uint32_t off =
                    (uint32_t)((wn + nt2 * 16 + brow) * KSTRIDE + kb + bcol8) * 2;
                ldsm4(bhf[nt2], stg + STG_B_H + off);
                ldsm4(blf[nt2], stg + STG_B_L + off);
            }
#pragma unroll
            for (int mt = 0; mt < 4; mt++)
#pragma unroll
                for (int nt = 0; nt < 4; nt++) {
                    const uint32_t* bh = &bhf[nt >> 1][(nt & 1) * 2];
                    const uint32_t* bl = &blf[nt >> 1][(nt & 1) * 2];
                    mma16816(acc[mt][nt], ahf[mt], bh);   // hi*hi
                    mma16816(acc[mt][nt], ahf[mt], bl);   // hi*lo
                    mma16816(acc[mt][nt], alf[mt], bh);   // lo*hi
                }
        }
        if (kt + 2 < ntiles) issue(kt + 2, (kt + 2) % 3);
    }

    // -------- epilogue --------
    const int g = lane >> 2;
    const int t = lane & 3;
#pragma unroll
    for (int mt = 0; mt < 4; mt++)
#pragma unroll
        for (int nt = 0; nt < 4; nt++) {
            const int gcol = bn + wn + nt * 8 + t * 2;
            float b0 = 0.f, b1 = 0.f;
            if (bias) { b0 = __ldg(&bias[gcol]); b1 = __ldg(&bias[gcol + 1]); }
#pragma unroll
            for (int half_ = 0; half_ < 2; half_++) {
                const int grow = bm + wmB + mt * 16 + g + half_ * 8;
                float v0 = acc[mt][nt][half_ * 2 + 0] + b0;
                float v1 = acc[mt][nt][half_ * 2 + 1] + b1;
                if (flags & 1) { v0 = fmaxf(v0, 0.f); v1 = fmaxf(v1, 0.f); }
                const size_t o = (size_t)grow * N + gcol;
                if (flags & 4) {
                    float2 w2 = make_float2(v0, v1);
                    *(float2*)(Cf + o) = w2;
                }
                if (flags & 2) {
                    const __half h0 = __float2half_rn(v0);
                    const __half h1 = __float2half_rn(v1);
                    const __half l0 = __float2half_rn(v0 - __half2float(h0));
                    const __half l1 = __float2half_rn(v1 - __half2float(h1));
                    *(__half2*)(Chh + o) = __halves2half2(h0, h1);
                    *(__half2*)(Chl + o) = __halves2half2(l0, l1);
                }
            }
        }
}

// ---------------------------------------------------------------------------
// Transpose + fp16-split weights: W[K,N] -> Wt_hi/lo[N,K]
// ---------------------------------------------------------------------------
__global__ void tsplit_kernel(const float* __restrict__ W, __half* __restrict__ Th,
                              __half* __restrict__ Tl, int Kd, int Nd)
{
    __shared__ float t[32][33];
    const int bx = blockIdx.x * 32;   // N
    const int by = blockIdx.y * 32;   // K
    const int x = threadIdx.x, y0 = threadIdx.y;
#pragma unroll
    for (int dy = 0; dy < 32; dy += 8)
        t[y0 + dy][x] = W[(size_t)(by + y0 + dy) * Nd + bx + x];
    __syncthreads();
#pragma unroll
    for (int dy = 0; dy < 32; dy += 8) {
        const float w = t[x][y0 + dy];
        const __half hi = __float2half_rn(w);
        const __half lo = __float2half_rn(w - __half2float(hi));
        const size_t o = (size_t)(bx + y0 + dy) * Kd + by + x;
        Th[o] = hi;
        Tl[o] = lo;
    }
}

// Elementwise fp16 split (for x).
__global__ void split_kernel(const float* __restrict__ in, __half* __restrict__ hi,
                             __half* __restrict__ lo, int n4)
{
    int i = blockIdx.x * blockDim.x + threadIdx.x;
    if (i >= n4) return;
    float4 a = ((const float4*)in)[i];
    __half h0 = __float2half_rn(a.x), h1 = __float2half_rn(a.y);
    __half h2 = __float2half_rn(a.z), h3 = __float2half_rn(a.w);
    __half l0 = __float2half_rn(a.x - __half2float(h0));
    __half l1 = __float2half_rn(a.y - __half2float(h1));
    __half l2 = __float2half_rn(a.z - __half2float(h2));
    __half l3 = __float2half_rn(a.w - __half2float(h3));
    ((__half2*)hi)[i * 2]     = __halves2half2(h0, h1);
    ((__half2*)hi)[i * 2 + 1] = __halves2half2(h2, h3);
    ((__half2*)lo)[i * 2]     = __halves2half2(l0, l1);
    ((__half2*)lo)[i * 2 + 1] = __halves2half2(l2, l3);
}

// ---------------------------------------------------------------------------
// Neighbor attention (K=8); fp32 q/k/v in, fp16-split ctx out.
// ---------------------------------------------------------------------------
__global__ __launch_bounds__(256)
void attn_kernel(const float* __restrict__ q, const float* __restrict__ kp,
                 const float* __restrict__ vp, const float* __restrict__ radj,
                 const int* __restrict__ inxs, __half* __restrict__ ch,
                 __half* __restrict__ cl)
{
    const int bt = blockIdx.x;
    const int b = bt >> 10;
    const int tid = threadIdx.x;
    const int wid = tid >> 5, lid = tid & 31;

    __shared__ float s_scores[KNEI];
    __shared__ int s_rows[KNEI];
    if (tid < KNEI) s_rows[tid] = b * TSEQ + inxs[(size_t)bt * KNEI + tid];
    __syncthreads();

    const float4* qv = (const float4*)(q + (size_t)bt * CDIM);
    const float4* kv = (const float4*)(kp + (size_t)s_rows[wid] * CDIM);
    float sum = 0.f;
#pragma unroll 4
    for (int e = lid; e < CDIM / 4; e += 32) {
        float4 a = qv[e], c = kv[e];
        sum += a.x * c.x + a.y * c.y + a.z * c.z + a.w * c.w;
    }
#pragma unroll
    for (int o = 16; o > 0; o >>= 1) sum += __shfl_xor_sync(0xffffffffu, sum, o);
    if (lid == 0)
        s_scores[wid] = sum * 0.03125f + radj[(size_t)bt * KNEI + wid];
    __syncthreads();

    float w[KNEI];
    float mx = s_scores[0];
#pragma unroll
    for (int j = 1; j < KNEI; j++) mx = fmaxf(mx, s_scores[j]);
    float den = 0.f;
#pragma unroll
    for (int j = 0; j < KNEI; j++) { w[j] = expf(s_scores[j] - mx); den += w[j]; }
    const float inv = 1.f / den;

    float4 o4 = make_float4(0.f, 0.f, 0.f, 0.f);
#pragma unroll
    for (int j = 0; j < KNEI; j++) {
        const float4 v = ((const float4*)(vp + (size_t)s_rows[j] * CDIM))[tid];
        const float wj = w[j] * inv;
        o4.x = fmaf(wj, v.x, o4.x); o4.y = fmaf(wj, v.y, o4.y);
        o4.z = fmaf(wj, v.z, o4.z); o4.w = fmaf(wj, v.w, o4.w);
    }
    __half h0 = __float2half_rn(o4.x), h1 = __float2half_rn(o4.y);
    __half h2 = __float2half_rn(o4.z), h3 = __float2half_rn(o4.w);
    __half l0 = __float2half_rn(o4.x - __half2float(h0));
    __half l1 = __float2half_rn(o4.y - __half2float(h1));
    __half l2 = __float2half_rn(o4.z - __half2float(h2));
    __half l3 = __float2half_rn(o4.w - __half2float(h3));
    const size_t base2 = (size_t)bt * (CDIM / 2) + tid * 2;
    ((__half2*)ch)[base2]     = __halves2half2(h0, h1);
    ((__half2*)ch)[base2 + 1] = __halves2half2(h2, h3);
    ((__half2*)cl)[base2]     = __halves2half2(l0, l1);
    ((__half2*)cl)[base2 + 1] = __halves2half2(l2, l3);
}

// ---------------------------------------------------------------------------
// Fused residual (+optional relu) LayerNorm; optional fp16-split extra output.
// ---------------------------------------------------------------------------
__global__ __launch_bounds__(256)
void ln_kernel(const float* __restrict__ a, const float* __restrict__ hb,
               const float* __restrict__ g, const float* __restrict__ beta,
               float* __restrict__ out, __half* __restrict__ oh,
               __half* __restrict__ ol, int relu_h)
{
    __shared__ float sh1[8], sh2[8];
    const int bt = blockIdx.x;
    const int tid = threadIdx.x;
    const int wid = tid >> 5, lid = tid & 31;
    const size_t base = (size_t)bt * CDIM;

    float4 z = ((const float4*)(a + base))[tid];
    float4 hh = ((const float4*)(hb + base))[tid];
    if (relu_h) {
        hh.x = fmaxf(hh.x, 0.f); hh.y = fmaxf(hh.y, 0.f);
        hh.z = fmaxf(hh.z, 0.f); hh.w = fmaxf(hh.w, 0.f);
    }
    z.x += hh.x; z.y += hh.y; z.z += hh.z; z.w += hh.w;

    float s = z.x + z.y + z.z + z.w;
    float ss = z.x * z.x + z.y * z.y + z.z * z.z + z.w * z.w;
#pragma unroll
    for (int o = 16; o > 0; o >>= 1) {
        s += __shfl_xor_sync(0xffffffffu, s, o);
        ss += __shfl_xor_sync(0xffffffffu, ss, o);
    }
    if (lid == 0) { sh1[wid] = s; sh2[wid] = ss; }
    __syncthreads();
    float ts = 0.f, tss = 0.f;
#pragma unroll
    for (int j = 0; j < 8; j++) { ts += sh1[j]; tss += sh2[j]; }

    const float mean = ts * (1.f / CDIM);
    const float var = tss * (1.f / CDIM) - mean * mean;
    const float rstd = rsqrtf(var + 1e-5f);

    const float4 gg = ((const float4*)g)[tid];
    const float4 bb = ((const float4*)beta)[tid];
    float4 o4;
    o4.x = (z.x - mean) * rstd * gg.x + bb.x;
    o4.y = (z.y - mean) * rstd * gg.y + bb.y;
    o4.z = (z.z - mean) * rstd * gg.z + bb.z;
    o4.w = (z.w - mean) * rstd * gg.w + bb.w;
    ((float4*)(out + base))[tid] = o4;
    if (oh) {
        __half h0 = __float2half_rn(o4.x), h1 = __float2half_rn(o4.y);
        __half h2 = __float2half_rn(o4.z), h3 = __float2half_rn(o4.w);
        __half l0 = __float2half_rn(o4.x - __half2float(h0));
        __half l1 = __float2half_rn(o4.y - __half2float(h1));
        __half l2 = __float2half_rn(o4.z - __half2float(h2));
        __half l3 = __float2half_rn(o4.w - __half2float(h3));
        const size_t b2 = (size_t)bt * (CDIM / 2) + tid * 2;
        ((__half2*)oh)[b2]     = __halves2half2(h0, h1);
        ((__half2*)oh)[b2 + 1] = __halves2half2(h2, h3);
        ((__half2*)ol)[b2]     = __halves2half2(l0, l1);
        ((__half2*)ol)[b2 + 1] = __halves2half2(l2, l3);
    }
}

// ---------------------------------------------------------------------------
// Launch
// ---------------------------------------------------------------------------
extern "C" void kernel_launch(void* const* d_in, const int* in_sizes, int n_in,
                              void* d_out, int out_size)
{
    const float* x    = (const float*)d_in[0];
    const float* radj = (const float*)d_in[1];
    const int*   inxs = (const int*)  d_in[2];
    const float* Wq   = (const float*)d_in[3];
    const float* Wk   = (const float*)d_in[4];
    const float* Wv   = (const float*)d_in[5];
    const float* Wo   = (const float*)d_in[6];
    const float* ln1g = (const float*)d_in[7];
    const float* ln1b = (const float*)d_in[8];
    const float* W1   = (const float*)d_in[9];
    const float* b1   = (const float*)d_in[10];
    const float* W2   = (const float*)d_in[11];
    const float* b2   = (const float*)d_in[12];
    const float* ln2g = (const float*)d_in[13];
    const float* ln2b = (const float*)d_in[14];
    float* out = (float*)d_out;

    float *q, *k, *v, *h32, *y, *f;
    __half *ctxh, *ctxl, *hh, *hl, *yh, *yl, *xh, *xl, *hidh, *hidl;
    __half *wqh, *wql, *wkh, *wkl, *wvh, *wvl, *woh, *wol, *w1h, *w1l, *w2h, *w2l;
    cudaGetSymbolAddress((void**)&q, g_q);       cudaGetSymbolAddress((void**)&k, g_k);
    cudaGetSymbolAddress((void**)&v, g_v);       cudaGetSymbolAddress((void**)&ctxh, g_ctxh);
    cudaGetSymbolAddress((void**)&ctxl, g_ctxl); cudaGetSymbolAddress((void**)&hh, g_hh);
    cudaGetSymbolAddress((void**)&hl, g_hl);     cudaGetSymbolAddress((void**)&h32, g_h32);
    cudaGetSymbolAddress((void**)&y, g_y);       cudaGetSymbolAddress((void**)&yh, g_yh);
    cudaGetSymbolAddress((void**)&yl, g_yl);     cudaGetSymbolAddress((void**)&f, g_f);
    cudaGetSymbolAddress((void**)&xh, g_xh);     cudaGetSymbolAddress((void**)&xl, g_xl);
    cudaGetSymbolAddress((void**)&hidh, g_hidh); cudaGetSymbolAddress((void**)&hidl, g_hidl);
    cudaGetSymbolAddress((void**)&wqh, g_wqh);   cudaGetSymbolAddress((void**)&wql, g_wql);
    cudaGetSymbolAddress((void**)&wkh, g_wkh);   cudaGetSymbolAddress((void**)&wkl, g_wkl);
    cudaGetSymbolAddress((void**)&wvh, g_wvh);   cudaGetSymbolAddress((void**)&wvl, g_wvl);
    cudaGetSymbolAddress((void**)&woh, g_woh);   cudaGetSymbolAddress((void**)&wol, g_wol);
    cudaGetSymbolAddress((void**)&w1h, g_w1h);   cudaGetSymbolAddress((void**)&w1l, g_w1l);
    cudaGetSymbolAddress((void**)&w2h, g_w2h);   cudaGetSymbolAddress((void**)&w2l, g_w2l);

    cudaFuncSetAttribute(mm_fp16x2_kernel,
                         cudaFuncAttributeMaxDynamicSharedMemorySize, MM_SMEM);

    const dim3 b256(256);
    const dim3 tblk(32, 8);

    // Weight transpose + split (fp16 hi/lo), x split.
    tsplit_kernel<<<dim3(CDIM / 32, CDIM / 32), tblk>>>(Wq, wqh, wql, CDIM, CDIM);
    tsplit_kernel<<<dim3(CDIM / 32, CDIM / 32), tblk>>>(Wk, wkh, wkl, CDIM, CDIM);
    tsplit_kernel<<<dim3(CDIM / 32, CDIM / 32), tblk>>>(Wv, wvh, wvl, CDIM, CDIM);
    tsplit_kernel<<<dim3(CDIM / 32, CDIM / 32), tblk>>>(Wo, woh, wol, CDIM, CDIM);
    tsplit_kernel<<<dim3(HDIM / 32, CDIM / 32), tblk>>>(W1, w1h, w1l, CDIM, HDIM);
    tsplit_kernel<<<dim3(CDIM / 32, HDIM / 32), tblk>>>(W2, w2h, w2l, HDIM, CDIM);
    split_kernel<<<(MDIM * CDIM / 4 + 255) / 256, b256>>>(x, xh, xl, MDIM * CDIM / 4);

    const dim3 gCC(CDIM / 128, MDIM / 128);   // (8, 128)
    const dim3 gCH(HDIM / 128, MDIM / 128);   // (12, 128)

    const __half *ah = xh, *al = xl;
    for (int hop = 0; hop < 2; hop++) {
        mm_fp16x2_kernel<<<gCC, 256, MM_SMEM>>>(ah, al, wqh, wql, q, nullptr, nullptr,
                                                nullptr, CDIM, CDIM, 4);
        mm_fp16x2_kernel<<<gCC, 256, MM_SMEM>>>(ah, al, wkh, wkl, k, nullptr, nullptr,
                                                nullptr, CDIM, CDIM, 4);
        mm_fp16x2_kernel<<<gCC, 256, MM_SMEM>>>(ah, al, wvh, wvl, v, nullptr, nullptr,
                                                nullptr, CDIM, CDIM, 4);
        attn_kernel<<<MDIM, b256>>>(q, k, v, radj, inxs, ctxh, ctxl);
        if (hop == 0) {
            mm_fp16x2_kernel<<<gCC, 256, MM_SMEM>>>(ctxh, ctxl, woh, wol, nullptr, hh, hl,
                                                    nullptr, CDIM, CDIM, 2);
            ah = hh; al = hl;
        } else {
            mm_fp16x2_kernel<<<gCC, 256, MM_SMEM>>>(ctxh, ctxl, woh, wol, h32, nullptr, nullptr,
                                                    nullptr, CDIM, CDIM, 4);
        }
    }

    // y = LN(x + relu(h));  + fp16 split for FFN input
    ln_kernel<<<MDIM, b256>>>(x, h32, ln1g, ln1b, y, yh, yl, 1);
    // hid = relu(y @ W1 + b1)  -> fp16 split
    mm_fp16x2_kernel<<<gCH, 256, MM_SMEM>>>(yh, yl, w1h, w1l, nullptr, hidh, hidl,
                                            b1, HDIM, CDIM, 1 | 2);
    // f = hid @ W2 + b2  -> fp32
    mm_fp16x2_kernel<<<gCC, 256, MM_SMEM>>>(hidh, hidl, w2h, w2l, f, nullptr, nullptr,
                                            b2, CDIM, HDIM, 4);
    // out = LN(y + f)
    ln_kernel<<<MDIM, b256>>>(y, f, ln2g, ln2b, out, nullptr, nullptr, 0);
}